// round 15
// baseline (speedup 1.0000x reference)
#include <cuda_runtime.h>
#include <cuda_bf16.h>
#include <cstdint>
#include <cstddef>

#define IN_DIM  512
#define OUT_DIM 256
#define NMID    1280
#define NNODES  1792
#define BATCH   16384
#define NB      10
#define NKCH    28            // 1792/64 k-chunks
#define NRB     128           // 16384/128 row blocks
#define TILE_E  8192          // bf16 elems per tile (128 rows x 64 k)
#define NTHR    512

// gmem tile images (SW128-swizzled) + fp32 diagonal blocks
__device__ unsigned short g_resT_hi[(size_t)NRB * NKCH * TILE_E];
__device__ unsigned short g_resT_lo[(size_t)NRB * NKCH * TILE_E];
__device__ unsigned short g_wT_hi[(size_t)NB * NKCH * TILE_E];
__device__ unsigned short g_wT_lo[(size_t)NB * NKCH * TILE_E];
__device__ float          g_Wdiag[(size_t)NB * 128 * 128];   // [t][j][i]

// ---------------- helpers ----------------
__device__ __forceinline__ uint32_t sw128(uint32_t b) { return b ^ ((b >> 3) & 0x70); }
__device__ __forceinline__ unsigned short f2bf(float f) {
    return __bfloat16_as_ushort(__float2bfloat16(f));
}
__device__ __forceinline__ float bfbits2f(uint32_t u) { return __uint_as_float(u << 16); }
__device__ __forceinline__ uint32_t smem_u32(const void* p) {
    uint32_t a;
    asm("{ .reg .u64 t; cvta.to.shared.u64 t, %1; cvt.u32.u64 %0, t; }" : "=r"(a) : "l"(p));
    return a;
}
#define MBAR_INIT(a, c) asm volatile("mbarrier.init.shared.b64 [%0], %1;" :: "r"(a), "r"(c) : "memory")
#define MBAR_TX(a, b)   asm volatile("mbarrier.arrive.expect_tx.shared.b64 _, [%0], %1;" :: "r"(a), "r"(b) : "memory")
#define MBAR_WAIT(a, p) do {                                                        \
    asm volatile("{\n\t.reg .pred P1;\n\t"                                          \
        "W_%=:\n\t"                                                                 \
        "mbarrier.try_wait.parity.acquire.cta.shared::cta.b64 P1, [%0], %1, 0x989680;\n\t" \
        "@P1 bra.uni D_%=;\n\t"                                                     \
        "bra.uni W_%=;\n\t"                                                         \
        "D_%=:\n\t}" :: "r"((uint32_t)(a)), "r"((uint32_t)(p)) : "memory");         \
} while (0)

__device__ __forceinline__ void bulk_g2s(uint32_t dst, const void* src, uint32_t bytes, uint32_t mbar) {
    asm volatile("cp.async.bulk.shared::cluster.global.mbarrier::complete_tx::bytes [%0], [%1], %2, [%3];"
                 :: "r"(dst), "l"(src), "r"(bytes), "r"(mbar) : "memory");
}
__device__ __forceinline__ void ldsm4(uint32_t& r0, uint32_t& r1, uint32_t& r2, uint32_t& r3, uint32_t a) {
    asm volatile("ldmatrix.sync.aligned.m8n8.x4.shared.b16 {%0,%1,%2,%3}, [%4];"
                 : "=r"(r0), "=r"(r1), "=r"(r2), "=r"(r3) : "r"(a));
}
__device__ __forceinline__ void mma16816(float* c, const uint32_t* a, uint32_t b0, uint32_t b1) {
    asm volatile("mma.sync.aligned.m16n8k16.row.col.f32.bf16.bf16.f32 "
        "{%0,%1,%2,%3}, {%4,%5,%6,%7}, {%8,%9}, {%0,%1,%2,%3};"
        : "+f"(c[0]), "+f"(c[1]), "+f"(c[2]), "+f"(c[3])
        : "r"(a[0]), "r"(a[1]), "r"(a[2]), "r"(a[3]), "r"(b0), "r"(b1));
}

// ---------------- prep: W^T -> swizzled bf16 hi/lo tiles ----------------
__global__ void prep_w_kernel(const float* __restrict__ w, const int* __restrict__ conn) {
    int idx = blockIdx.x * blockDim.x + threadIdx.x;        // one 4-elem group
    if (idx >= NB * NKCH * 2048) return;
    int r = idx & 127, tk4 = (idx >> 7) & 15, tile = idx >> 11;
    int kc = tile % NKCH, t = tile / NKCH;
    int c = t * 128 + r;
    unsigned short hh[4], ll[4];
#pragma unroll
    for (int q = 0; q < 4; q++) {
        int k = kc * 64 + tk4 * 4 + q;
        float f = w[(size_t)k * NMID + c] * (float)conn[(size_t)k * NMID + c];
        hh[q] = f2bf(f);
        ll[q] = f2bf(f - bfbits2f(hh[q]));
    }
    uint32_t off = (uint32_t)tile * TILE_E + (sw128((uint32_t)(r * 128 + tk4 * 8)) >> 1);
    *(uint2*)&g_wT_hi[off] = make_uint2(hh[0] | ((uint32_t)hh[1] << 16), hh[2] | ((uint32_t)hh[3] << 16));
    *(uint2*)&g_wT_lo[off] = make_uint2(ll[0] | ((uint32_t)ll[1] << 16), ll[2] | ((uint32_t)ll[3] << 16));
}
__global__ void prep_wd_kernel(const float* __restrict__ w, const int* __restrict__ conn) {
    int idx = blockIdx.x * blockDim.x + threadIdx.x;
    if (idx >= NB * 128 * 128) return;
    int i = idx & 127, j = (idx >> 7) & 127, t = idx >> 14;
    size_t src = (size_t)(IN_DIM + t * 128 + j) * NMID + t * 128 + i;
    g_Wdiag[idx] = w[src] * (float)conn[src];
}
// ---------------- init: x -> res tiles (chunks 0..7) ----------------
__global__ void init_x_kernel(const float* __restrict__ x) {
    int idx = blockIdx.x * blockDim.x + threadIdx.x;        // one 4-elem group
    if (idx >= BATCH * 128) return;
    int k4 = idx & 127, b = idx >> 7;
    float4 v = *(const float4*)&x[(size_t)b * IN_DIM + k4 * 4];
    float f[4] = {v.x, v.y, v.z, v.w};
    unsigned short hh[4], ll[4];
#pragma unroll
    for (int q = 0; q < 4; q++) { hh[q] = f2bf(f[q]); ll[q] = f2bf(f[q] - bfbits2f(hh[q])); }
    int rb = b >> 7, tr = b & 127, kc = k4 >> 4, tk4 = k4 & 15;
    uint32_t off = (uint32_t)(rb * NKCH + kc) * TILE_E + (sw128((uint32_t)(tr * 128 + tk4 * 8)) >> 1);
    *(uint2*)&g_resT_hi[off] = make_uint2(hh[0] | ((uint32_t)hh[1] << 16), hh[2] | ((uint32_t)hh[3] << 16));
    *(uint2*)&g_resT_lo[off] = make_uint2(ll[0] | ((uint32_t)ll[1] << 16), ll[2] | ((uint32_t)ll[3] << 16));
}

// ---------------- fused kernel ----------------
// smem: [0,131072) 2 stages of {Ahi,Alo,Bhi,Blo} 16KB; P fp32 [128][133] overlays
//       [131072,196608) Wd fp32 [j][i]; then sbv, sev, mbarriers
#define SM_STAGE 65536
#define SM_WD    131072
#define SM_SBV   196608
#define SM_SEV   197120
#define SM_BARS  197632   // full0 +0, full1 +8, wd +16
#define SMEM_SZ  197696

__device__ __forceinline__ void load_chunk(uint32_t sb32, int rb, int t, int c, int s) {
    uint32_t mbar = sb32 + SM_BARS + s * 8;
    uint32_t stg  = sb32 + s * SM_STAGE;
    MBAR_TX(mbar, 65536);
    size_t a = ((size_t)rb * NKCH + c) * TILE_E;
    size_t b = ((size_t)t  * NKCH + c) * TILE_E;
    bulk_g2s(stg,         &g_resT_hi[a], 16384, mbar);
    bulk_g2s(stg + 16384, &g_resT_lo[a], 16384, mbar);
    bulk_g2s(stg + 32768, &g_wT_hi[b],   16384, mbar);
    bulk_g2s(stg + 49152, &g_wT_lo[b],   16384, mbar);
}

__global__ void __launch_bounds__(NTHR, 1)
fused_kernel(const float* __restrict__ bias, const int* __restrict__ exist,
             float* __restrict__ out) {
    extern __shared__ char smem[];
    const uint32_t sb32 = smem_u32(smem);
    float* P   = (float*)smem;                  // [128][133] overlays stages
    float* Wd  = (float*)(smem + SM_WD);        // [j][i]
    float* sbv = (float*)(smem + SM_SBV);
    float* sev = (float*)(smem + SM_SEV);
    const int tid = threadIdx.x, wid = tid >> 5, lane = tid & 31;
    const int rb = blockIdx.x;
    const int warp_m = wid & 3, warp_n = wid >> 2;   // 4 x 4 warp grid, 32x32 tiles

    if (tid == 0) { for (int i = 0; i < 3; i++) MBAR_INIT(sb32 + SM_BARS + i * 8, 1); }
    __syncthreads();

    int f0 = 0, f1 = 0, fw = 0;   // mbarrier phase ledger (per thread)

    for (int t = 0; t < NB; t++) {
        const int c0 = t * 128, nch = 8 + 2 * t;

        if (tid == 0) {
            asm volatile("fence.proxy.async;" ::: "memory");
            load_chunk(sb32, rb, t, 0, 0);
            load_chunk(sb32, rb, t, 1, 1);
            MBAR_TX(sb32 + SM_BARS + 16, 65536);
            bulk_g2s(sb32 + SM_WD, &g_Wdiag[(size_t)t * 16384], 65536, sb32 + SM_BARS + 16);
        }

        float acc[2][4][4];
#pragma unroll
        for (int mi = 0; mi < 2; mi++)
#pragma unroll
            for (int ni = 0; ni < 4; ni++)
#pragma unroll
                for (int q = 0; q < 4; q++) acc[mi][ni][q] = 0.f;

        for (int c = 0; c < nch; c++) {
            int s = c & 1;
            uint32_t stg = sb32 + s * SM_STAGE;
            if (s == 0) { MBAR_WAIT(sb32 + SM_BARS + 0, f0); f0 ^= 1; }
            else        { MBAR_WAIT(sb32 + SM_BARS + 8, f1); f1 ^= 1; }

#pragma unroll
            for (int ks = 0; ks < 4; ks++) {
                // ---- load ALL fragments for this k-step first ----
                uint32_t ah[2][4], al[2][4], bh[2][4], bl[2][4];
#pragma unroll
                for (int mi = 0; mi < 2; mi++) {
                    int row = 32 * warp_m + 16 * mi + (lane & 15);
                    uint32_t adr = stg + sw128((uint32_t)(row * 128 + ks * 32 + ((lane >> 4) << 4)));
                    ldsm4(ah[mi][0], ah[mi][1], ah[mi][2], ah[mi][3], adr);
                    ldsm4(al[mi][0], al[mi][1], al[mi][2], al[mi][3], adr + 16384);
                }
#pragma unroll
                for (int p = 0; p < 2; p++) {
                    int brow = 32 * warp_n + p * 16 + (lane & 7) + ((lane >> 4) << 3);
                    uint32_t badr = stg + 32768 +
                        sw128((uint32_t)(brow * 128 + ks * 32 + (((lane >> 3) & 1) << 4)));
                    ldsm4(bh[p][0], bh[p][1], bh[p][2], bh[p][3], badr);
                    ldsm4(bl[p][0], bl[p][1], bl[p][2], bl[p][3], badr + 16384);
                }
                // ---- term-major MMA order ----
#pragma unroll
                for (int mi = 0; mi < 2; mi++)
#pragma unroll
                    for (int p = 0; p < 2; p++)
#pragma unroll
                        for (int q = 0; q < 2; q++)
                            mma16816(acc[mi][2 * p + q], ah[mi], bh[p][2 * q], bh[p][2 * q + 1]);
#pragma unroll
                for (int mi = 0; mi < 2; mi++)
#pragma unroll
                    for (int p = 0; p < 2; p++)
#pragma unroll
                        for (int q = 0; q < 2; q++)
                            mma16816(acc[mi][2 * p + q], al[mi], bh[p][2 * q], bh[p][2 * q + 1]);
#pragma unroll
                for (int mi = 0; mi < 2; mi++)
#pragma unroll
                    for (int p = 0; p < 2; p++)
#pragma unroll
                        for (int q = 0; q < 2; q++)
                            mma16816(acc[mi][2 * p + q], ah[mi], bl[p][2 * q], bl[p][2 * q + 1]);
            }
            __syncthreads();                       // stage s fully consumed
            if (tid == 0 && c + 2 < nch) load_chunk(sb32, rb, t, c + 2, s);
        }

        // ---- epilogue: accumulators -> P (stages now free) ----
#pragma unroll
        for (int mi = 0; mi < 2; mi++)
#pragma unroll
            for (int ni = 0; ni < 4; ni++) {
                int r0 = 32 * warp_m + 16 * mi + (lane >> 2);
                int cc = 32 * warp_n + 8 * ni + 2 * (lane & 3);
                P[r0 * 133 + cc]           = acc[mi][ni][0];
                P[r0 * 133 + cc + 1]       = acc[mi][ni][1];
                P[(r0 + 8) * 133 + cc]     = acc[mi][ni][2];
                P[(r0 + 8) * 133 + cc + 1] = acc[mi][ni][3];
            }
        if (tid < 128) {
            sbv[tid] = bias[c0 + tid];
            sev[tid] = (float)exist[c0 + tid];
        }
        MBAR_WAIT(sb32 + SM_BARS + 16, fw); fw ^= 1;   // Wd landed
        __syncthreads();

        // ---- sweep: 8 sub-blocks of 16 (dense rank-update + register triangle) ----
        for (int s = 0; s < 8; s++) {
            {   // dense: P[r][i] += sum_{j<16s} P[r][j] * Wd[j][i]  (512 thr, 4 cols)
                int r = tid & 127, i0 = s * 16 + (tid >> 7) * 4;
                float a[4];
#pragma unroll
                for (int ii = 0; ii < 4; ii++) a[ii] = P[r * 133 + i0 + ii];
                for (int j = 0; j < s * 16; j++) {
                    float pv = P[r * 133 + j];
                    float4 w0 = *(const float4*)&Wd[j * 128 + i0];
                    a[0] += pv * w0.x; a[1] += pv * w0.y;
                    a[2] += pv * w0.z; a[3] += pv * w0.w;
                }
#pragma unroll
                for (int ii = 0; ii < 4; ii++) P[r * 133 + i0 + ii] = a[ii];
            }
            __syncthreads();
            if (tid < 128) {   // serial 16x16 triangle: values live in registers
                float* Pr = &P[(size_t)tid * 133 + s * 16];
                const float* Wb = &Wd[(s * 16) * 128 + s * 16];
                float pv[16];
#pragma unroll
                for (int i = 0; i < 16; i++) {
                    float a = Pr[i];
#pragma unroll
                    for (int j = 0; j < i; j++)
                        a += pv[j] * Wb[j * 128 + i];     // Wb: warp-uniform broadcast
                    float v = 1.0f / (1.0f + __expf(-a));
                    int gi = s * 16 + i;
                    pv[i] = (v + sbv[gi]) * sev[gi];
                    Pr[i] = pv[i];
                }
            }
            __syncthreads();
        }

        // ---- writeback: bf16 hi/lo tile images for later panels ----
        if (t < 9) {
            for (int half = 0; half < 2; half++) {
                size_t tb = ((size_t)rb * NKCH + 8 + 2 * t + half) * TILE_E;
                for (int idx = tid; idx < 128 * 32; idx += NTHR) {
                    int r = idx >> 5, kp = (idx & 31) * 2;
                    float v0 = P[r * 133 + half * 64 + kp];
                    float v1 = P[r * 133 + half * 64 + kp + 1];
                    unsigned short h0 = f2bf(v0), h1 = f2bf(v1);
                    unsigned short l0 = f2bf(v0 - bfbits2f(h0));
                    unsigned short l1 = f2bf(v1 - bfbits2f(h1));
                    uint32_t off = sw128((uint32_t)(r * 128 + kp * 2)) >> 1;
                    *(uint32_t*)&g_resT_hi[tb + off] = (uint32_t)h0 | ((uint32_t)h1 << 16);
                    *(uint32_t*)&g_resT_lo[tb + off] = (uint32_t)l0 | ((uint32_t)l1 << 16);
                }
            }
        }
        if (t >= 8) {   // panels 8,9 are the 256 output nodes
            for (int idx = tid; idx < 128 * 128; idx += NTHR) {
                int r = idx >> 7, c = idx & 127;
                out[((size_t)rb * 128 + r) * OUT_DIM + (t - 8) * 128 + c] = P[r * 133 + c];
            }
        }
        __threadfence();
        __syncthreads();
    }
}

// ---------------------------------------------------------------------------
extern "C" void kernel_launch(void* const* d_in, const int* in_sizes, int n_in,
                              void* d_out, int out_size) {
    const float* x     = (const float*)d_in[0];
    const float* w     = (const float*)d_in[1];
    const float* bias  = (const float*)d_in[2];
    const int*   conn  = (const int*)d_in[3];
    const int*   exist = (const int*)d_in[4];
    float* out = (float*)d_out;

    cudaFuncSetAttribute(fused_kernel, cudaFuncAttributeMaxDynamicSharedMemorySize, SMEM_SZ);

    prep_w_kernel<<<(NB * NKCH * 2048 + 255) / 256, 256>>>(w, conn);
    prep_wd_kernel<<<(NB * 128 * 128 + 255) / 256, 256>>>(w, conn);
    init_x_kernel<<<(BATCH * 128 + 255) / 256, 256>>>(x);
    fused_kernel<<<NRB, NTHR, SMEM_SZ>>>(bias, exist, out);
}

// round 16
// speedup vs baseline: 1.9110x; 1.9110x over previous
#include <cuda_runtime.h>
#include <cuda_bf16.h>
#include <cstdint>
#include <cstddef>

#define IN_DIM  512
#define OUT_DIM 256
#define NMID    1280
#define NNODES  1792
#define BATCH   16384
#define NB      10            // max panels (worst case, all exist)
#define NKCH    28            // max k-chunks
#define NRB     128           // 16384/128 row blocks
#define TILE_E  8192          // bf16 elems per tile (128 rows x 64 k)

// gmem tile images (SW128-swizzled) + fp32 diagonal blocks (compacted node space)
__device__ unsigned short g_resT_hi[(size_t)NRB * NKCH * TILE_E];
__device__ unsigned short g_resT_lo[(size_t)NRB * NKCH * TILE_E];
__device__ unsigned short g_wT_hi[(size_t)NB * NKCH * TILE_E];
__device__ unsigned short g_wT_lo[(size_t)NB * NKCH * TILE_E];
__device__ float          g_Wdiag[(size_t)NB * 128 * 128];   // [t][j][i]

// compaction state
__device__ int   g_cmap[NMID];    // compacted idx -> original mid idx (-1 = pad)
__device__ float g_cbias[NMID];   // compacted bias (0 for pad)
__device__ float g_csev[NMID];    // 1 for real node, 0 for pad
__device__ int   g_E, g_npan;

// ---------------- helpers ----------------
__device__ __forceinline__ uint32_t sw128(uint32_t b) { return b ^ ((b >> 3) & 0x70); }
__device__ __forceinline__ unsigned short f2bf(float f) {
    return __bfloat16_as_ushort(__float2bfloat16(f));
}
__device__ __forceinline__ float bfbits2f(uint32_t u) { return __uint_as_float(u << 16); }
__device__ __forceinline__ uint32_t smem_u32(const void* p) {
    uint32_t a;
    asm("{ .reg .u64 t; cvta.to.shared.u64 t, %1; cvt.u32.u64 %0, t; }" : "=r"(a) : "l"(p));
    return a;
}
#define MBAR_INIT(a, c) asm volatile("mbarrier.init.shared.b64 [%0], %1;" :: "r"(a), "r"(c) : "memory")
#define MBAR_TX(a, b)   asm volatile("mbarrier.arrive.expect_tx.shared.b64 _, [%0], %1;" :: "r"(a), "r"(b) : "memory")
#define MBAR_WAIT(a, p) do {                                                        \
    asm volatile("{\n\t.reg .pred P1;\n\t"                                          \
        "W_%=:\n\t"                                                                 \
        "mbarrier.try_wait.parity.acquire.cta.shared::cta.b64 P1, [%0], %1, 0x989680;\n\t" \
        "@P1 bra.uni D_%=;\n\t"                                                     \
        "bra.uni W_%=;\n\t"                                                         \
        "D_%=:\n\t}" :: "r"((uint32_t)(a)), "r"((uint32_t)(p)) : "memory");         \
} while (0)

__device__ __forceinline__ void bulk_g2s(uint32_t dst, const void* src, uint32_t bytes, uint32_t mbar) {
    asm volatile("cp.async.bulk.shared::cluster.global.mbarrier::complete_tx::bytes [%0], [%1], %2, [%3];"
                 :: "r"(dst), "l"(src), "r"(bytes), "r"(mbar) : "memory");
}
__device__ __forceinline__ void ldsm4(uint32_t& r0, uint32_t& r1, uint32_t& r2, uint32_t& r3, uint32_t a) {
    asm volatile("ldmatrix.sync.aligned.m8n8.x4.shared.b16 {%0,%1,%2,%3}, [%4];"
                 : "=r"(r0), "=r"(r1), "=r"(r2), "=r"(r3) : "r"(a));
}
__device__ __forceinline__ void mma16816(float* c, const uint32_t* a, uint32_t b0, uint32_t b1) {
    asm volatile("mma.sync.aligned.m16n8k16.row.col.f32.bf16.bf16.f32 "
        "{%0,%1,%2,%3}, {%4,%5,%6,%7}, {%8,%9}, {%0,%1,%2,%3};"
        : "+f"(c[0]), "+f"(c[1]), "+f"(c[2]), "+f"(c[3])
        : "r"(a[0]), "r"(a[1]), "r"(a[2]), "r"(a[3]), "r"(b0), "r"(b1));
}

// ---------------- scan: build compacted node map ----------------
__global__ void scan_kernel(const float* __restrict__ bias, const int* __restrict__ exist) {
    __shared__ int ps[256];
    int tid = threadIdx.x;
    int base = tid * 5;                       // 1280 = 256 * 5
    int loc[5], cnt = 0;
#pragma unroll
    for (int q = 0; q < 5; q++) { loc[q] = exist[base + q]; cnt += loc[q]; }
    ps[tid] = cnt;
    __syncthreads();
    for (int off = 1; off < 256; off <<= 1) {
        int v = (tid >= off) ? ps[tid - off] : 0;
        __syncthreads();
        ps[tid] += v;
        __syncthreads();
    }
    int pos = ps[tid] - cnt;                  // exclusive prefix
#pragma unroll
    for (int q = 0; q < 5; q++) {
        if (loc[q]) {
            g_cmap[pos]  = base + q;
            g_cbias[pos] = bias[base + q];
            g_csev[pos]  = 1.0f;
            pos++;
        }
    }
    if (tid == 255) {
        int E = ps[255];
        g_E = E;
        int npan = (E + 127) >> 7;
        g_npan = npan;
        int epad = npan << 7;
        for (int e = E; e < epad; e++) { g_cmap[e] = -1; g_cbias[e] = 0.f; g_csev[e] = 0.f; }
    }
}

// ---------------- prep: compacted W^T -> swizzled bf16 hi/lo tiles ----------------
__global__ void prep_w_kernel(const float* __restrict__ w, const int* __restrict__ conn) {
    int idx = blockIdx.x * blockDim.x + threadIdx.x;        // one 4-elem group
    if (idx >= NB * NKCH * 2048) return;
    int r = idx & 127, tk4 = (idx >> 7) & 15, tile = idx >> 11;
    int kc = tile % NKCH, t = tile / NKCH;
    if (t >= g_npan || kc >= 8 + 2 * t) return;
    int m = g_cmap[t * 128 + r];              // orig mid column (-1 pad)
    unsigned short hh[4], ll[4];
#pragma unroll
    for (int q = 0; q < 4; q++) {
        int s = kc * 64 + tk4 * 4 + q;        // compacted state row
        int ok;                               // original node row
        if (s < IN_DIM) ok = s;
        else { int mm = g_cmap[s - IN_DIM]; ok = (mm >= 0) ? IN_DIM + mm : -1; }
        float f = 0.f;
        if (ok >= 0 && m >= 0) {
            size_t src = (size_t)ok * NMID + m;
            f = w[src] * (float)conn[src];
        }
        hh[q] = f2bf(f);
        ll[q] = f2bf(f - bfbits2f(hh[q]));
    }
    uint32_t off = (uint32_t)tile * TILE_E + (sw128((uint32_t)(r * 128 + tk4 * 8)) >> 1);
    *(uint2*)&g_wT_hi[off] = make_uint2(hh[0] | ((uint32_t)hh[1] << 16), hh[2] | ((uint32_t)hh[3] << 16));
    *(uint2*)&g_wT_lo[off] = make_uint2(ll[0] | ((uint32_t)ll[1] << 16), ll[2] | ((uint32_t)ll[3] << 16));
}
__global__ void prep_wd_kernel(const float* __restrict__ w, const int* __restrict__ conn) {
    int idx = blockIdx.x * blockDim.x + threadIdx.x;
    if (idx >= NB * 128 * 128) return;
    int i = idx & 127, j = (idx >> 7) & 127, t = idx >> 14;
    if (t >= g_npan) return;
    int jm = g_cmap[t * 128 + j], im = g_cmap[t * 128 + i];
    float v = 0.f;
    if (jm >= 0 && im >= 0) {
        size_t src = (size_t)(IN_DIM + jm) * NMID + im;
        v = w[src] * (float)conn[src];
    }
    g_Wdiag[idx] = v;
}
// ---------------- init: x -> res tiles (chunks 0..7) ----------------
__global__ void init_x_kernel(const float* __restrict__ x) {
    int idx = blockIdx.x * blockDim.x + threadIdx.x;        // one 4-elem group
    if (idx >= BATCH * 128) return;
    int k4 = idx & 127, b = idx >> 7;
    float4 v = *(const float4*)&x[(size_t)b * IN_DIM + k4 * 4];
    float f[4] = {v.x, v.y, v.z, v.w};
    unsigned short hh[4], ll[4];
#pragma unroll
    for (int q = 0; q < 4; q++) { hh[q] = f2bf(f[q]); ll[q] = f2bf(f[q] - bfbits2f(hh[q])); }
    int rb = b >> 7, tr = b & 127, kc = k4 >> 4, tk4 = k4 & 15;
    uint32_t off = (uint32_t)(rb * NKCH + kc) * TILE_E + (sw128((uint32_t)(tr * 128 + tk4 * 8)) >> 1);
    *(uint2*)&g_resT_hi[off] = make_uint2(hh[0] | ((uint32_t)hh[1] << 16), hh[2] | ((uint32_t)hh[3] << 16));
    *(uint2*)&g_resT_lo[off] = make_uint2(ll[0] | ((uint32_t)ll[1] << 16), ll[2] | ((uint32_t)ll[3] << 16));
}

// ---------------- fused kernel (256 threads, 64x32 warp tiles — proven config) ----------------
#define SM_STAGE 65536
#define SM_WD    131072
#define SM_SBV   196608
#define SM_SEV   197120
#define SM_BARS  197632   // full0 +0, full1 +8, wd +16
#define SMEM_SZ  197696

__device__ __forceinline__ void load_chunk(uint32_t sb32, int rb, int t, int c, int s) {
    uint32_t mbar = sb32 + SM_BARS + s * 8;
    uint32_t stg  = sb32 + s * SM_STAGE;
    MBAR_TX(mbar, 65536);
    size_t a = ((size_t)rb * NKCH + c) * TILE_E;
    size_t b = ((size_t)t  * NKCH + c) * TILE_E;
    bulk_g2s(stg,         &g_resT_hi[a], 16384, mbar);
    bulk_g2s(stg + 16384, &g_resT_lo[a], 16384, mbar);
    bulk_g2s(stg + 32768, &g_wT_hi[b],   16384, mbar);
    bulk_g2s(stg + 49152, &g_wT_lo[b],   16384, mbar);
}

__global__ void __launch_bounds__(256, 1)
fused_kernel(float* __restrict__ out) {
    extern __shared__ char smem[];
    const uint32_t sb32 = smem_u32(smem);
    float* P   = (float*)smem;                  // [128][133] overlays stages
    float* Wd  = (float*)(smem + SM_WD);        // [j][i]
    float* sbv = (float*)(smem + SM_SBV);
    float* sev = (float*)(smem + SM_SEV);
    const int tid = threadIdx.x, wid = tid >> 5, lane = tid & 31;
    const int rb = blockIdx.x;
    const int warp_m = wid & 1, warp_n = wid >> 1;   // 2 x 4 warp grid, 64x32 tiles
    const int npan = g_npan, E = g_E;
    const int obase = E - OUT_DIM;                   // first output col (compacted)

    if (tid == 0) { for (int i = 0; i < 3; i++) MBAR_INIT(sb32 + SM_BARS + i * 8, 1); }
    __syncthreads();

    int f0 = 0, f1 = 0, fw = 0;   // mbarrier phase ledger (per thread)

    for (int t = 0; t < npan; t++) {
        const int c0 = t * 128, nch = 8 + 2 * t;

        if (tid == 0) {
            asm volatile("fence.proxy.async;" ::: "memory");
            load_chunk(sb32, rb, t, 0, 0);
            load_chunk(sb32, rb, t, 1, 1);
            MBAR_TX(sb32 + SM_BARS + 16, 65536);
            bulk_g2s(sb32 + SM_WD, &g_Wdiag[(size_t)t * 16384], 65536, sb32 + SM_BARS + 16);
        }

        float acc[4][4][4];
#pragma unroll
        for (int mi = 0; mi < 4; mi++)
#pragma unroll
            for (int ni = 0; ni < 4; ni++)
#pragma unroll
                for (int q = 0; q < 4; q++) acc[mi][ni][q] = 0.f;

        for (int c = 0; c < nch; c++) {
            int s = c & 1;
            uint32_t stg = sb32 + s * SM_STAGE;
            if (s == 0) { MBAR_WAIT(sb32 + SM_BARS + 0, f0); f0 ^= 1; }
            else        { MBAR_WAIT(sb32 + SM_BARS + 8, f1); f1 ^= 1; }

#pragma unroll
            for (int ks = 0; ks < 4; ks++) {
                // ---- load ALL fragments for this k-step first ----
                uint32_t ah[4][4], al[4][4], bh[2][4], bl[2][4];
#pragma unroll
                for (int mi = 0; mi < 4; mi++) {
                    int row = 64 * warp_m + 16 * mi + (lane & 15);
                    uint32_t adr = stg + sw128((uint32_t)(row * 128 + ks * 32 + ((lane >> 4) << 4)));
                    ldsm4(ah[mi][0], ah[mi][1], ah[mi][2], ah[mi][3], adr);
                    ldsm4(al[mi][0], al[mi][1], al[mi][2], al[mi][3], adr + 16384);
                }
#pragma unroll
                for (int p = 0; p < 2; p++) {
                    int brow = 32 * warp_n + p * 16 + (lane & 7) + ((lane >> 4) << 3);
                    uint32_t badr = stg + 32768 +
                        sw128((uint32_t)(brow * 128 + ks * 32 + (((lane >> 3) & 1) << 4)));
                    ldsm4(bh[p][0], bh[p][1], bh[p][2], bh[p][3], badr);
                    ldsm4(bl[p][0], bl[p][1], bl[p][2], bl[p][3], badr + 16384);
                }
                // ---- term-major MMA order: same-acc reuse distance = 16 ----
#pragma unroll
                for (int mi = 0; mi < 4; mi++)
#pragma unroll
                    for (int p = 0; p < 2; p++)
#pragma unroll
                        for (int q = 0; q < 2; q++)
                            mma16816(acc[mi][2 * p + q], ah[mi], bh[p][2 * q], bh[p][2 * q + 1]);
#pragma unroll
                for (int mi = 0; mi < 4; mi++)
#pragma unroll
                    for (int p = 0; p < 2; p++)
#pragma unroll
                        for (int q = 0; q < 2; q++)
                            mma16816(acc[mi][2 * p + q], al[mi], bh[p][2 * q], bh[p][2 * q + 1]);
#pragma unroll
                for (int mi = 0; mi < 4; mi++)
#pragma unroll
                    for (int p = 0; p < 2; p++)
#pragma unroll
                        for (int q = 0; q < 2; q++)
                            mma16816(acc[mi][2 * p + q], ah[mi], bl[p][2 * q], bl[p][2 * q + 1]);
            }
            __syncthreads();                       // stage s fully consumed
            if (tid == 0 && c + 2 < nch) load_chunk(sb32, rb, t, c + 2, s);
        }

        // ---- epilogue: accumulators -> P (stages now free) ----
#pragma unroll
        for (int mi = 0; mi < 4; mi++)
#pragma unroll
            for (int ni = 0; ni < 4; ni++) {
                int r0 = 64 * warp_m + 16 * mi + (lane >> 2);
                int cc = 32 * warp_n + 8 * ni + 2 * (lane & 3);
                P[r0 * 133 + cc]           = acc[mi][ni][0];
                P[r0 * 133 + cc + 1]       = acc[mi][ni][1];
                P[(r0 + 8) * 133 + cc]     = acc[mi][ni][2];
                P[(r0 + 8) * 133 + cc + 1] = acc[mi][ni][3];
            }
        if (tid < 128) {
            sbv[tid] = g_cbias[c0 + tid];
            sev[tid] = g_csev[c0 + tid];
        }
        MBAR_WAIT(sb32 + SM_BARS + 16, fw); fw ^= 1;   // Wd landed
        __syncthreads();

        // ---- sweep: 8 sub-blocks of 16 (dense rank-update + register triangle) ----
        for (int s = 0; s < 8; s++) {
            {   // dense: P[r][i] += sum_{j<16s} P[r][j] * Wd[j][i]
                int r = tid & 127, i0 = s * 16 + (tid >> 7) * 8;
                float a[8];
#pragma unroll
                for (int ii = 0; ii < 8; ii++) a[ii] = P[r * 133 + i0 + ii];
                for (int j = 0; j < s * 16; j++) {
                    float pv = P[r * 133 + j];
                    float4 w0 = *(const float4*)&Wd[j * 128 + i0];
                    float4 w1 = *(const float4*)&Wd[j * 128 + i0 + 4];
                    a[0] += pv * w0.x; a[1] += pv * w0.y;
                    a[2] += pv * w0.z; a[3] += pv * w0.w;
                    a[4] += pv * w1.x; a[5] += pv * w1.y;
                    a[6] += pv * w1.z; a[7] += pv * w1.w;
                }
#pragma unroll
                for (int ii = 0; ii < 8; ii++) P[r * 133 + i0 + ii] = a[ii];
            }
            __syncthreads();
            if (tid < 128) {   // serial 16x16 triangle: values live in registers
                float* Pr = &P[(size_t)tid * 133 + s * 16];
                const float* Wb = &Wd[(s * 16) * 128 + s * 16];
                float pv[16];
#pragma unroll
                for (int i = 0; i < 16; i++) {
                    float a = Pr[i];
#pragma unroll
                    for (int j = 0; j < i; j++)
                        a += pv[j] * Wb[j * 128 + i];     // Wb: warp-uniform broadcast
                    float v = 1.0f / (1.0f + __expf(-a));
                    int gi = s * 16 + i;
                    pv[i] = (v + sbv[gi]) * sev[gi];
                    Pr[i] = pv[i];
                }
            }
            __syncthreads();
        }

        // ---- writeback: bf16 hi/lo tile images for later panels ----
        if (t + 1 < npan) {
            for (int half = 0; half < 2; half++) {
                size_t tb = ((size_t)rb * NKCH + 8 + 2 * t + half) * TILE_E;
                for (int idx = tid; idx < 128 * 32; idx += 256) {
                    int r = idx >> 5, kp = (idx & 31) * 2;
                    float v0 = P[r * 133 + half * 64 + kp];
                    float v1 = P[r * 133 + half * 64 + kp + 1];
                    unsigned short h0 = f2bf(v0), h1 = f2bf(v1);
                    unsigned short l0 = f2bf(v0 - bfbits2f(h0));
                    unsigned short l1 = f2bf(v1 - bfbits2f(h1));
                    uint32_t off = sw128((uint32_t)(r * 128 + kp * 2)) >> 1;
                    *(uint32_t*)&g_resT_hi[tb + off] = (uint32_t)h0 | ((uint32_t)h1 << 16);
                    *(uint32_t*)&g_resT_lo[tb + off] = (uint32_t)l0 | ((uint32_t)l1 << 16);
                }
            }
        }
        if (c0 + 127 >= obase) {   // panel contains output columns
            for (int idx = tid; idx < 128 * 128; idx += 256) {
                int r = idx >> 7, c = idx & 127;
                int off = c0 + c - obase;
                if (off >= 0 && off < OUT_DIM)
                    out[((size_t)rb * 128 + r) * OUT_DIM + off] = P[r * 133 + c];
            }
        }
        __threadfence();
        __syncthreads();
    }
}

// ---------------------------------------------------------------------------
extern "C" void kernel_launch(void* const* d_in, const int* in_sizes, int n_in,
                              void* d_out, int out_size) {
    const float* x     = (const float*)d_in[0];
    const float* w     = (const float*)d_in[1];
    const float* bias  = (const float*)d_in[2];
    const int*   conn  = (const int*)d_in[3];
    const int*   exist = (const int*)d_in[4];
    float* out = (float*)d_out;

    cudaFuncSetAttribute(fused_kernel, cudaFuncAttributeMaxDynamicSharedMemorySize, SMEM_SZ);

    scan_kernel<<<1, 256>>>(bias, exist);
    prep_w_kernel<<<(NB * NKCH * 2048 + 255) / 256, 256>>>(w, conn);
    prep_wd_kernel<<<(NB * 128 * 128 + 255) / 256, 256>>>(w, conn);
    init_x_kernel<<<(BATCH * 128 + 255) / 256, 256>>>(x);
    fused_kernel<<<NRB, 256, SMEM_SZ>>>(out);
}